// round 17
// baseline (speedup 1.0000x reference)
#include <cuda_runtime.h>
#include <cuda_fp16.h>
#include <math.h>
#include <stdint.h>

#define N_NODES 20000
#define NTOT    40000
#define MPAD2   40192
#define MT2     314
#define N_EDGES 640000
#define FIN_DIM 256
#define HDIM 512
#define TOPK 1000
#define SELN 4096
#define WSLOT 131072

// ---------------- scratch (static device memory; no allocations) ----------------
__device__ __half   g_xh[(size_t)NTOT * FIN_DIM];
__device__ __half   g_aggh[(size_t)MPAD2 * HDIM];
__device__ __half   g_acth[(size_t)MPAD2 * HDIM];
__device__ __half   g_tmph[(size_t)MPAD2 * HDIM];
__device__ uint32_t g_wh[6 * WSLOT];
__device__ float    g_part[8][MPAD2][2];
__device__ float    g_top[TOPK];
__device__ int      g_cnt[NTOT];
__device__ int      g_rowptr[2 * (N_NODES + 1)];
__device__ int      g_cursor[NTOT];
__device__ int      g_esrc[2 * N_EDGES];

// ---------------- helpers ----------------
__device__ __forceinline__ void mma_f16(float* c, const uint32_t* a, const uint32_t* b) {
    asm volatile(
        "mma.sync.aligned.m16n8k16.row.col.f32.f16.f16.f32 "
        "{%0,%1,%2,%3}, {%4,%5,%6,%7}, {%8,%9}, {%0,%1,%2,%3};"
        : "+f"(c[0]), "+f"(c[1]), "+f"(c[2]), "+f"(c[3])
        : "r"(a[0]), "r"(a[1]), "r"(a[2]), "r"(a[3]), "r"(b[0]), "r"(b[1]));
}

// ---------------- combined conversion: inputs + weights -> fp16 ------------
#define XWORK (NTOT * (FIN_DIM / 4))                       // 2,560,000 float4s
#define WWORK ((FIN_DIM / 2 + 5 * (HDIM / 2)) * HDIM)      // 720,896 words
__global__ void k_conv(const float* __restrict__ xa, const float* __restrict__ xb,
                       const float* __restrict__ w11, const float* __restrict__ w12,
                       const float* __restrict__ w21, const float* __restrict__ w22,
                       const float* __restrict__ w31, const float* __restrict__ w32,
                       __half* __restrict__ xout) {
    int i = blockIdx.x * blockDim.x + threadIdx.x;
    if (i < XWORK) {
        int gph = i >= N_NODES * (FIN_DIM / 4);
        int local = i - gph * N_NODES * (FIN_DIM / 4);
        float4 v = ((const float4*)(gph ? xb : xa))[local];
        __half2 h0 = __floats2half2_rn(v.x, v.y);
        __half2 h1 = __floats2half2_rn(v.z, v.w);
        ((uint2*)xout)[i] = make_uint2(*(uint32_t*)&h0, *(uint32_t*)&h1);
        return;
    }
    int j = i - XWORK;
    if (j >= WWORK) return;
    const int S0 = (FIN_DIM / 2) * HDIM;
    const int SN = (HDIM / 2) * HDIM;
    int slot, local;
    if (j < S0) { slot = 0; local = j; }
    else {
        int q = j - S0;
        slot = 1 + q / SN;
        local = q - (slot - 1) * SN;
    }
    const float* W;
    switch (slot) {
        case 0: W = w11; break;
        case 1: W = w12; break;
        case 2: W = w21; break;
        case 3: W = w22; break;
        case 4: W = w31; break;
        default: W = w32; break;
    }
    int k2 = local / HDIM;
    int n = local - k2 * HDIM;
    __half2 h = __floats2half2_rn(W[(size_t)(2 * k2) * HDIM + n],
                                  W[(size_t)(2 * k2 + 1) * HDIM + n]);
    g_wh[slot * WSLOT + local] = *(uint32_t*)&h;
}

// ---------------- CSR build (both graphs, batched) ----------------
__global__ void k_hist2(const int* __restrict__ dst1, const int* __restrict__ dst2) {
    int e = blockIdx.x * blockDim.x + threadIdx.x;
    if (e >= 2 * N_EDGES) return;
    int gph = e >= N_EDGES;
    int le = e - gph * N_EDGES;
    int d = (gph ? dst2 : dst1)[le];
    atomicAdd(&g_cnt[gph * N_NODES + d], 1);
}
__global__ void k_scan2() {
    const int PER = 20;
    int gph = blockIdx.x;
    int t = threadIdx.x, lane = t & 31, wid = t >> 5;
    const int cbase = gph * N_NODES;
    const int rbase = gph * (N_NODES + 1);
    int base = t * PER;
    int v[PER];
    int sum = 0;
#pragma unroll
    for (int i = 0; i < PER; i++) {
        int idx = base + i;
        v[i] = (idx < N_NODES) ? g_cnt[cbase + idx] : 0;
        sum += v[i];
    }
    int s = sum;
#pragma unroll
    for (int off = 1; off < 32; off <<= 1) {
        int n = __shfl_up_sync(0xffffffffu, s, off);
        if (lane >= off) s += n;
    }
    __shared__ int wsum[32];
    if (lane == 31) wsum[wid] = s;
    __syncthreads();
    if (wid == 0) {
        int ws = wsum[lane];
#pragma unroll
        for (int off = 1; off < 32; off <<= 1) {
            int n = __shfl_up_sync(0xffffffffu, ws, off);
            if (lane >= off) ws += n;
        }
        wsum[lane] = ws;
    }
    __syncthreads();
    int excl = s - sum + (wid > 0 ? wsum[wid - 1] : 0);
    int run = excl;
#pragma unroll
    for (int i = 0; i < PER; i++) {
        int idx = base + i;
        if (idx < N_NODES) {
            g_rowptr[rbase + idx] = run;
            g_cursor[cbase + idx] = run;
        }
        run += v[i];
    }
    if (t == 1023) g_rowptr[rbase + N_NODES] = run;
}
__global__ void k_fill2(const int* __restrict__ src1, const int* __restrict__ dst1,
                        const int* __restrict__ src2, const int* __restrict__ dst2) {
    int e = blockIdx.x * blockDim.x + threadIdx.x;
    if (e >= 2 * N_EDGES) return;
    int gph = e >= N_EDGES;
    int le = e - gph * N_EDGES;
    int d = (gph ? dst2 : dst1)[le];
    int sv = (gph ? src2 : src1)[le];
    int pos = atomicAdd(&g_cursor[gph * N_NODES + d], 1);
    g_esrc[gph * N_EDGES + pos] = sv;
}

// ---------------- aggregation (fp16 in, fp16 out), templated on F ----------
template <int F>
__global__ void k_aggh(const __half* __restrict__ x, __half* __restrict__ out) {
    const int TPN = F / 8;
    const int NPB = 512 / TPN;
    int t = threadIdx.x;
    int node = blockIdx.x * NPB + t / TPN;
    int tf = t % TPN;
    if (node >= NTOT) return;
    int gph = node >= N_NODES;
    int local = node - gph * N_NODES;
    const uint4* x4 = (const uint4*)x;
    float acc[8];
    {
        uint4 v = x4[(size_t)node * TPN + tf];
        float2 f0 = __half22float2(*(__half2*)&v.x);
        float2 f1 = __half22float2(*(__half2*)&v.y);
        float2 f2 = __half22float2(*(__half2*)&v.z);
        float2 f3 = __half22float2(*(__half2*)&v.w);
        acc[0] = f0.x; acc[1] = f0.y; acc[2] = f1.x; acc[3] = f1.y;
        acc[4] = f2.x; acc[5] = f2.y; acc[6] = f3.x; acc[7] = f3.y;
    }
    int beg = g_rowptr[gph * (N_NODES + 1) + local];
    int end = g_rowptr[gph * (N_NODES + 1) + local + 1];
    const int* ep = g_esrc + gph * N_EDGES;
    const size_t gofs = (size_t)gph * N_NODES * TPN;
    int e = beg;
    for (; e + 1 < end; e += 2) {
        int i0 = __ldg(&ep[e]);
        int i1 = __ldg(&ep[e + 1]);
        uint4 v0 = x4[gofs + (size_t)i0 * TPN + tf];
        uint4 v1 = x4[gofs + (size_t)i1 * TPN + tf];
        float2 a0 = __half22float2(*(__half2*)&v0.x), b0 = __half22float2(*(__half2*)&v1.x);
        float2 a1 = __half22float2(*(__half2*)&v0.y), b1 = __half22float2(*(__half2*)&v1.y);
        float2 a2 = __half22float2(*(__half2*)&v0.z), b2 = __half22float2(*(__half2*)&v1.z);
        float2 a3 = __half22float2(*(__half2*)&v0.w), b3 = __half22float2(*(__half2*)&v1.w);
        acc[0] += a0.x + b0.x; acc[1] += a0.y + b0.y;
        acc[2] += a1.x + b1.x; acc[3] += a1.y + b1.y;
        acc[4] += a2.x + b2.x; acc[5] += a2.y + b2.y;
        acc[6] += a3.x + b3.x; acc[7] += a3.y + b3.y;
    }
    if (e < end) {
        int i0 = __ldg(&ep[e]);
        uint4 v0 = x4[gofs + (size_t)i0 * TPN + tf];
        float2 a0 = __half22float2(*(__half2*)&v0.x);
        float2 a1 = __half22float2(*(__half2*)&v0.y);
        float2 a2 = __half22float2(*(__half2*)&v0.z);
        float2 a3 = __half22float2(*(__half2*)&v0.w);
        acc[0] += a0.x; acc[1] += a0.y; acc[2] += a1.x; acc[3] += a1.y;
        acc[4] += a2.x; acc[5] += a2.y; acc[6] += a3.x; acc[7] += a3.y;
    }
    __half2 h0 = __floats2half2_rn(acc[0], acc[1]);
    __half2 h1 = __floats2half2_rn(acc[2], acc[3]);
    __half2 h2 = __floats2half2_rn(acc[4], acc[5]);
    __half2 h3 = __floats2half2_rn(acc[6], acc[7]);
    uint4 u = make_uint4(*(uint32_t*)&h0, *(uint32_t*)&h1,
                         *(uint32_t*)&h2, *(uint32_t*)&h3);
    ((uint4*)out)[(size_t)node * TPN + tf] = u;
}

// ---------------- single-pass fp16 mma.sync GEMM with pre-packed W ---------
#define GSTRIDE 140
#define GMATW   (8 * GSTRIDE)

template <typename TC>
__global__ void __launch_bounds__(256)
k_gemm_mma(const __half* __restrict__ A, const uint32_t* __restrict__ W2,
           const float* __restrict__ bias, TC* __restrict__ C, int K,
           const float* __restrict__ linw2, float* __restrict__ part) {
    __shared__ uint32_t S[2][2][GMATW];
    int t = threadIdx.x, lane = t & 31, wid = t >> 5;
    int warp_m = wid >> 1, warp_n = wid & 1;
    int rowBase = blockIdx.y * 128;
    int colBase = blockIdx.x * 128;

    float acc[2][8][4];
#pragma unroll
    for (int i = 0; i < 2; i++)
#pragma unroll
        for (int j = 0; j < 8; j++)
#pragma unroll
            for (int q = 0; q < 4; q++) acc[i][j][q] = 0.f;

    int a_row = t >> 1;
    int a_half = t & 1;
    int b_k2 = t >> 5;
    int b_n0 = lane * 4;

    const __half* Ap = A + (size_t)(rowBase + a_row) * K + a_half * 8;
    const uint32_t* Bp = W2 + (size_t)b_k2 * HDIM + colBase + b_n0;

    const int nk = K >> 4;
    uint4 rah, rbw;

    rah = *(const uint4*)(Ap);
    rbw = *(const uint4*)(Bp);

    for (int s = 0; s < nk; s++) {
        int buf = s & 1;
        uint32_t* Aw = S[buf][0];
        uint32_t* Bh = S[buf][1];
        {
            Aw[(a_half * 4 + 0) * GSTRIDE + a_row] = rah.x;
            Aw[(a_half * 4 + 1) * GSTRIDE + a_row] = rah.y;
            Aw[(a_half * 4 + 2) * GSTRIDE + a_row] = rah.z;
            Aw[(a_half * 4 + 3) * GSTRIDE + a_row] = rah.w;
            *(uint4*)&Bh[b_k2 * GSTRIDE + b_n0] = rbw;
        }
        __syncthreads();
        if (s + 1 < nk) {
            rah = *(const uint4*)(Ap + (s + 1) * 16);
            rbw = *(const uint4*)(Bp + (size_t)(s + 1) * 8 * HDIM);
        }
        {
            int g = lane >> 2, q = lane & 3;
            uint32_t bhf[8][2];
#pragma unroll
            for (int nt = 0; nt < 8; nt++) {
                int n = warp_n * 64 + nt * 8 + g;
                bhf[nt][0] = Bh[q * GSTRIDE + n];
                bhf[nt][1] = Bh[(q + 4) * GSTRIDE + n];
            }
#pragma unroll
            for (int mt = 0; mt < 2; mt++) {
                int m = warp_m * 32 + mt * 16 + g;
                uint32_t ahf[4];
                ahf[0] = Aw[q * GSTRIDE + m];
                ahf[1] = Aw[q * GSTRIDE + m + 8];
                ahf[2] = Aw[(q + 4) * GSTRIDE + m];
                ahf[3] = Aw[(q + 4) * GSTRIDE + m + 8];
#pragma unroll
                for (int nt = 0; nt < 8; nt++) {
                    mma_f16(acc[mt][nt], ahf, bhf[nt]);
                }
            }
        }
    }

    int g = lane >> 2;
    int cq = (lane & 3) * 2;
    if (linw2 == nullptr) {
#pragma unroll
        for (int mt = 0; mt < 2; mt++) {
            int row = rowBase + warp_m * 32 + mt * 16 + g;
#pragma unroll
            for (int nt = 0; nt < 8; nt++) {
                int col = colBase + warp_n * 64 + nt * 8 + cq;
                float b0 = bias[col], b1 = bias[col + 1];
                float o0x = fmaxf(acc[mt][nt][0] + b0, 0.f);
                float o0y = fmaxf(acc[mt][nt][1] + b1, 0.f);
                float o1x = fmaxf(acc[mt][nt][2] + b0, 0.f);
                float o1y = fmaxf(acc[mt][nt][3] + b1, 0.f);
                if constexpr (sizeof(TC) == 2) {
                    __half2 p0 = __floats2half2_rn(o0x, o0y);
                    __half2 p1 = __floats2half2_rn(o1x, o1y);
                    *(__half2*)((__half*)C + (size_t)row * HDIM + col) = p0;
                    *(__half2*)((__half*)C + (size_t)(row + 8) * HDIM + col) = p1;
                } else {
                    *(float2*)((float*)C + (size_t)row * HDIM + col) = make_float2(o0x, o0y);
                    *(float2*)((float*)C + (size_t)(row + 8) * HDIM + col) = make_float2(o1x, o1y);
                }
            }
        }
    } else {
        int slot = blockIdx.x * 2 + warp_n;
#pragma unroll
        for (int mt = 0; mt < 2; mt++) {
            float s00 = 0.f, s01 = 0.f;
            float s10 = 0.f, s11 = 0.f;
#pragma unroll
            for (int nt = 0; nt < 8; nt++) {
                int col = colBase + warp_n * 64 + nt * 8 + cq;
                float b0 = bias[col], b1 = bias[col + 1];
                float lw00 = linw2[col * 2],     lw01 = linw2[col * 2 + 1];
                float lw10 = linw2[col * 2 + 2], lw11 = linw2[col * 2 + 3];
                float v0 = fmaxf(acc[mt][nt][0] + b0, 0.f);
                float v1 = fmaxf(acc[mt][nt][1] + b1, 0.f);
                float v2 = fmaxf(acc[mt][nt][2] + b0, 0.f);
                float v3 = fmaxf(acc[mt][nt][3] + b1, 0.f);
                s00 += v0 * lw00 + v1 * lw10;
                s01 += v0 * lw01 + v1 * lw11;
                s10 += v2 * lw00 + v3 * lw10;
                s11 += v2 * lw01 + v3 * lw11;
            }
#pragma unroll
            for (int off = 1; off <= 2; off <<= 1) {
                s00 += __shfl_xor_sync(0xffffffffu, s00, off);
                s01 += __shfl_xor_sync(0xffffffffu, s01, off);
                s10 += __shfl_xor_sync(0xffffffffu, s10, off);
                s11 += __shfl_xor_sync(0xffffffffu, s11, off);
            }
            if ((lane & 3) == 0) {
                int row = rowBase + warp_m * 32 + mt * 16 + g;
                float* p0 = part + ((size_t)slot * MPAD2 + row) * 2;
                p0[0] = s00; p0[1] = s01;
                float* p1 = part + ((size_t)slot * MPAD2 + row + 8) * 2;
                p1[0] = s10; p1[1] = s11;
            }
        }
    }
}

// ---------------- fused top-k: linred + dist + histogram + compact + sort --
__device__ __forceinline__ float sel_dist(int i, float lb0, float lb1) {
    // o[i] reconstructed in EXACT k_linred order: bias, then slots 0..7
    float a0 = lb0, a1 = lb1, c0 = lb0, c1 = lb1;
#pragma unroll
    for (int s = 0; s < 8; s++) {
        a0 += g_part[s][i][0];
        a1 += g_part[s][i][1];
        c0 += g_part[s][i + N_NODES][0];
        c1 += g_part[s][i + N_NODES][1];
    }
    float dx = a0 - c0 + 1e-6f;
    float dy = a1 - c1 + 1e-6f;
    return sqrtf(dx * dx + dy * dy);
}
__global__ void k_select(const float* __restrict__ linb) {
    __shared__ int hist[2048];
    __shared__ float sel[SELN];
    __shared__ int cnt;
    __shared__ int thr;
    int t = threadIdx.x;
    float lb0 = linb[0], lb1 = linb[1];
    hist[t] = 0; hist[t + 1024] = 0;
    if (t == 0) cnt = 0;
    __syncthreads();
    for (int i = t; i < N_NODES; i += 1024) {
        float d = sel_dist(i, lb0, lb1);
        atomicAdd(&hist[__float_as_uint(d) >> 21], 1);
    }
    __syncthreads();
    if (t == 0) {
        int cum = 0, b;
        for (b = 2047; b >= 0; b--) {
            cum += hist[b];
            if (cum >= TOPK) break;
        }
        thr = b;
    }
    for (int i = t; i < SELN; i += 1024) sel[i] = -INFINITY;
    __syncthreads();
    int thrb = thr;
    for (int i = t; i < N_NODES; i += 1024) {
        float d = sel_dist(i, lb0, lb1);
        if ((int)(__float_as_uint(d) >> 21) >= thrb) {
            int pos = atomicAdd(&cnt, 1);
            if (pos < SELN) sel[pos] = d;
        }
    }
    __syncthreads();
    for (int k = 2; k <= SELN; k <<= 1) {
        for (int j = k >> 1; j > 0; j >>= 1) {
            for (int i = t; i < SELN; i += 1024) {
                int ixj = i ^ j;
                if (ixj > i) {
                    bool dsc = (i & k) == 0;
                    float a = sel[i], c = sel[ixj];
                    bool sw = dsc ? (a < c) : (a > c);
                    if (sw) { sel[i] = c; sel[ixj] = a; }
                }
            }
            __syncthreads();
        }
    }
    if (t < TOPK) g_top[t] = sel[t];
}

// ---------------- head MLP ----------------
__global__ void k_mlp(const float* __restrict__ fc1w, const float* __restrict__ fc1b,
                      const float* __restrict__ ln1g, const float* __restrict__ ln1b,
                      const float* __restrict__ fc2w, const float* __restrict__ fc2b,
                      const float* __restrict__ ln2g, const float* __restrict__ ln2b,
                      const float* __restrict__ fc3w, const float* __restrict__ fc3b,
                      float* __restrict__ out) {
    __shared__ float vals[TOPK];
    __shared__ float h1[128];
    __shared__ float part[4][128];
    __shared__ float h2[512];
    __shared__ float red[512];
    int t = threadIdx.x;
    for (int i = t; i < TOPK; i += 512) vals[i] = g_top[i];
    __syncthreads();
    {
        int j = t & 127, c = t >> 7;
        float acc = 0.f;
        for (int i = c * 250; i < (c + 1) * 250; i++) acc += vals[i] * fc1w[i * 128 + j];
        part[c][j] = acc;
    }
    __syncthreads();
    if (t < 128) h1[t] = part[0][t] + part[1][t] + part[2][t] + part[3][t] + fc1b[t];
    __syncthreads();
    red[t] = (t < 128) ? h1[t] : 0.f;
    __syncthreads();
    for (int off = 256; off; off >>= 1) { if (t < off) red[t] += red[t + off]; __syncthreads(); }
    float mean1 = red[0] / 128.f;
    __syncthreads();
    red[t] = (t < 128) ? (h1[t] - mean1) * (h1[t] - mean1) : 0.f;
    __syncthreads();
    for (int off = 256; off; off >>= 1) { if (t < off) red[t] += red[t + off]; __syncthreads(); }
    float var1 = red[0] / 128.f;
    __syncthreads();
    if (t < 128) {
        float v = (h1[t] - mean1) * rsqrtf(var1 + 1e-5f) * ln1g[t] + ln1b[t];
        h1[t] = fmaxf(v, 0.f);
    }
    __syncthreads();
    {
        float acc = fc2b[t];
        for (int i = 0; i < 128; i++) acc += h1[i] * fc2w[i * 512 + t];
        h2[t] = acc;
    }
    __syncthreads();
    red[t] = h2[t];
    __syncthreads();
    for (int off = 256; off; off >>= 1) { if (t < off) red[t] += red[t + off]; __syncthreads(); }
    float mean2 = red[0] / 512.f;
    __syncthreads();
    red[t] = (h2[t] - mean2) * (h2[t] - mean2);
    __syncthreads();
    for (int off = 256; off; off >>= 1) { if (t < off) red[t] += red[t + off]; __syncthreads(); }
    float var2 = red[0] / 512.f;
    __syncthreads();
    float hr = fmaxf((h2[t] - mean2) * rsqrtf(var2 + 1e-5f) * ln2g[t] + ln2b[t], 0.f);
    red[t] = hr * fc3w[t];
    __syncthreads();
    for (int off = 256; off; off >>= 1) { if (t < off) red[t] += red[t + off]; __syncthreads(); }
    if (t == 0) out[0] = 1.f / (1.f + expf(-(red[0] + fc3b[0])));
}

// ---------------- launch ----------------
extern "C" void kernel_launch(void* const* d_in, const int* in_sizes, int n_in,
                              void* d_out, int out_size) {
    const float* x1   = (const float*)d_in[0];
    const int*   ei1  = (const int*)d_in[1];
    const float* x2   = (const float*)d_in[2];
    const int*   ei2  = (const int*)d_in[3];
    const float* w11  = (const float*)d_in[4];
    const float* b11  = (const float*)d_in[5];
    const float* w12  = (const float*)d_in[6];
    const float* b12  = (const float*)d_in[7];
    const float* w21  = (const float*)d_in[8];
    const float* b21  = (const float*)d_in[9];
    const float* w22  = (const float*)d_in[10];
    const float* b22  = (const float*)d_in[11];
    const float* w31  = (const float*)d_in[12];
    const float* b31  = (const float*)d_in[13];
    const float* w32  = (const float*)d_in[14];
    const float* b32  = (const float*)d_in[15];
    const float* linw = (const float*)d_in[16];
    const float* linb = (const float*)d_in[17];
    const float* fc1w = (const float*)d_in[18];
    const float* fc1b = (const float*)d_in[19];
    const float* ln1g = (const float*)d_in[20];
    const float* ln1b = (const float*)d_in[21];
    const float* fc2w = (const float*)d_in[22];
    const float* fc2b = (const float*)d_in[23];
    const float* ln2g = (const float*)d_in[24];
    const float* ln2b = (const float*)d_in[25];
    const float* fc3w = (const float*)d_in[26];
    const float* fc3b = (const float*)d_in[27];
    float* out = (float*)d_out;

    const int* src1 = ei1;
    const int* dst1 = ei1 + N_EDGES;
    const int* src2 = ei2;
    const int* dst2 = ei2 + N_EDGES;

    __half *p_xh, *p_aggh, *p_acth, *p_tmph;
    uint32_t* p_wh;
    float* p_part;
    int* p_cnt;
    cudaGetSymbolAddress((void**)&p_xh, g_xh);
    cudaGetSymbolAddress((void**)&p_aggh, g_aggh);
    cudaGetSymbolAddress((void**)&p_acth, g_acth);
    cudaGetSymbolAddress((void**)&p_tmph, g_tmph);
    cudaGetSymbolAddress((void**)&p_wh, g_wh);
    cudaGetSymbolAddress((void**)&p_part, g_part);
    cudaGetSymbolAddress((void**)&p_cnt, g_cnt);

    dim3 ggrid(HDIM / 128, MT2);
    const int E2B = (2 * N_EDGES + 255) / 256;
    const int AGB512 = (NTOT + 7) / 8;
    const int AGB256 = (NTOT + 15) / 16;
    const int CVB = (XWORK + WWORK + 255) / 256;

    // zero degree counters via memset node (no kernel launch)
    cudaMemsetAsync(p_cnt, 0, NTOT * sizeof(int));

    // combined input+weight fp16 conversion (independent of CSR)
    k_conv<<<CVB, 256>>>(x1, x2, w11, w12, w21, w22, w31, w32, p_xh);

    // batched CSR for both graphs
    k_hist2<<<E2B, 256>>>(dst1, dst2);
    k_scan2<<<2, 1024>>>();
    k_fill2<<<E2B, 256>>>(src1, dst1, src2, dst2);

    // layer 1 (FIN=256 -> H)
    k_aggh<FIN_DIM><<<AGB256, 512>>>(p_xh, p_aggh);
    k_gemm_mma<__half><<<ggrid, 256>>>(p_aggh, p_wh + 0 * WSLOT, b11, p_tmph, FIN_DIM, nullptr, nullptr);
    k_gemm_mma<__half><<<ggrid, 256>>>(p_tmph, p_wh + 1 * WSLOT, b12, p_acth, HDIM, nullptr, nullptr);
    // layer 2
    k_aggh<HDIM><<<AGB512, 512>>>(p_acth, p_aggh);
    k_gemm_mma<__half><<<ggrid, 256>>>(p_aggh, p_wh + 2 * WSLOT, b21, p_tmph, HDIM, nullptr, nullptr);
    k_gemm_mma<__half><<<ggrid, 256>>>(p_tmph, p_wh + 3 * WSLOT, b22, p_acth, HDIM, nullptr, nullptr);
    // layer 3
    k_aggh<HDIM><<<AGB512, 512>>>(p_acth, p_aggh);
    k_gemm_mma<__half><<<ggrid, 256>>>(p_aggh, p_wh + 4 * WSLOT, b31, p_tmph, HDIM, nullptr, nullptr);
    // last GEMM: fused final linear -> partials
    k_gemm_mma<float><<<ggrid, 256>>>(p_tmph, p_wh + 5 * WSLOT, b32, (float*)nullptr, HDIM, linw, p_part);

    // fused linred + dist + select + sort, then head MLP
    k_select<<<1, 1024>>>(linb);
    k_mlp<<<1, 512>>>(fc1w, fc1b, ln1g, ln1b, fc2w, fc2b, ln2g, ln2b, fc3w, fc3b, out);
}